// round 9
// baseline (speedup 1.0000x reference)
#include <cuda_runtime.h>
#include <cuda_bf16.h>
#include <math.h>

#define B_    32
#define EMB_  256
#define HID_  516
#define G4_   2064     // 4*HID_
#define V_    32000
#define ROWS_ 2048     // 64*32 decoder rows
#define NK_   528      // K padded to multiple of 16
#define NK2_  264      // NK_/2 (u32 units)
#define NKI_  33       // k-iterations of 16
#define SROW_ 536      // smem row stride (u16), ldmatrix conflict-free; 1072B = 67 uint4
#define XROW_ 264      // smem row stride (u16) for K=256 tiles
#define NPAD_ 2112     // gate-col dim padded (66 tiles * 32)
#define SCANB_ 132     // scan blocks (<=148, all co-resident)
#define CROW2_ 72      // CE A-chunk row stride (u16), 64 cols + pad

// ---------------- scratch (static device globals; no allocation) ----------------
__device__ __nv_bfloat16 g_Wb[6][NPAD_ * NK_];        // scan weights bf16, gate-interleaved [j*4+g][k]
__device__ __nv_bfloat16 g_Wxb[2][NPAD_ * EMB_];      // Wih0 enc/dec bf16 interleaved (K=256)
__device__ __nv_bfloat16 g_xb[2][ROWS_ * EMB_];       // gathered embeddings bf16 [t*32+b][k]
__device__ float         g_pre[2][ROWS_ * G4_];       // input proj + bias, gate-interleaved
__device__ __nv_bfloat16 g_hb[2][2][B_ * NK_];        // h state [layer][buf], bf16 k-padded
__device__ float         g_c[2][B_ * HID_];           // c state fp32
__device__ __nv_bfloat16 g_histb[ROWS_ * NK_ + 64];   // decoder h1 history bf16 (+pad)
__device__ float         g_biasI0[2][G4_];            // layer0 bias (folded into pre)
__device__ float         g_biasI1[2][G4_];            // layer1 bias
__device__ float         g_sumexp[ROWS_];
__device__ float         g_tgt[ROWS_];
__device__ unsigned      g_cnt;                       // grid barrier arrivals (monotonic)

// ---------------- helpers ----------------
__device__ __forceinline__ unsigned smem_u32(const void* p) {
    return (unsigned)__cvta_generic_to_shared(p);
}
__device__ __forceinline__ void ldsm4(unsigned a[4], unsigned addr) {
    asm volatile("ldmatrix.sync.aligned.m8n8.x4.shared.b16 {%0,%1,%2,%3}, [%4];"
        : "=r"(a[0]), "=r"(a[1]), "=r"(a[2]), "=r"(a[3]) : "r"(addr));
}
__device__ __forceinline__ void mma_bf16(float c[4], const unsigned a[4], unsigned b0, unsigned b1) {
    asm volatile("mma.sync.aligned.m16n8k16.row.col.f32.bf16.bf16.f32 "
        "{%0,%1,%2,%3},{%4,%5,%6,%7},{%8,%9},{%0,%1,%2,%3};"
        : "+f"(c[0]), "+f"(c[1]), "+f"(c[2]), "+f"(c[3])
        : "r"(a[0]), "r"(a[1]), "r"(a[2]), "r"(a[3]), "r"(b0), "r"(b1));
}
__device__ __forceinline__ float sigf(float x) { return 1.f / (1.f + __expf(-x)); }
__device__ __forceinline__ unsigned short bfc(float v) {
    return __bfloat16_as_ushort(__float2bfloat16(v));
}

// ---------------- setup: init state + reduction buffers + fold biases ----------------
__global__ void setup_kernel(
    const float* eb0a, const float* eb0b, const float* db0a, const float* db0b,
    const float* eb1a, const float* eb1b, const float* db1a, const float* db1b)
{
    const int stride = gridDim.x * blockDim.x;
    const int i0 = blockIdx.x * blockDim.x + threadIdx.x;
    const __nv_bfloat16 z = __float2bfloat16(0.f);
    for (int i = i0; i < B_ * NK_; i += stride) {
        g_hb[0][0][i] = z; g_hb[0][1][i] = z;
        g_hb[1][0][i] = z; g_hb[1][1][i] = z;
    }
    for (int i = i0; i < B_ * HID_; i += stride) { g_c[0][i] = 0.f; g_c[1][i] = 0.f; }
    for (int i = i0; i < ROWS_; i += stride)     { g_sumexp[i] = 0.f; g_tgt[i] = 0.f; }
    // zero hist pad cols (516..527) so CE mma on pads is 0*0
    for (int i = i0; i < ROWS_ * 12; i += stride) {
        int r = i / 12, k = HID_ + i - r * 12;
        g_histb[r * NK_ + k] = z;
    }
    // fold biases (gate-interleaved)
    for (int t = i0; t < 2 * G4_; t += stride) {
        int sel = t / G4_, n = t - sel * G4_;
        int j = n >> 2, g = n & 3;
        g_biasI0[sel][n] = (sel ? db0a : eb0a)[g * HID_ + j] + (sel ? db0b : eb0b)[g * HID_ + j];
        g_biasI1[sel][n] = (sel ? db1a : eb1a)[g * HID_ + j] + (sel ? db1b : eb1b)[g * HID_ + j];
    }
    if (blockIdx.x == 0 && threadIdx.x == 0) g_cnt = 0u;
}

// ---------------- weight conversions ----------------
struct Ptrs6 { const float* p[6]; };
struct Ptrs2 { const float* p[2]; };

__global__ __launch_bounds__(256) void conv_gate_all(Ptrs6 ps) {
    const int slot = blockIdx.y;
    const float* __restrict__ src = ps.p[slot];
    int idx = blockIdx.x * blockDim.x + threadIdx.x;   // over NPAD_*264 (u32 pairs)
    if (idx >= NPAD_ * NK2_) return;
    int n = idx / NK2_, q = idx - n * NK2_, k = q * 2;
    float2 v = make_float2(0.f, 0.f);
    if (n < G4_ && k < HID_) {
        int j = n >> 2, g = n & 3;
        v = *(const float2*)&src[(size_t)(g * HID_ + j) * HID_ + k];
    }
    unsigned o = ((unsigned)bfc(v.y) << 16) | (unsigned)bfc(v.x);
    *(unsigned*)&g_Wb[slot][n * NK_ + k] = o;
}

__global__ __launch_bounds__(256) void conv_gate_x(Ptrs2 ps) {
    const int slot = blockIdx.y;
    const float* __restrict__ src = ps.p[slot];
    int idx = blockIdx.x * blockDim.x + threadIdx.x;   // over NPAD_*128
    if (idx >= NPAD_ * (EMB_ / 2)) return;
    int n = idx / (EMB_ / 2), q = idx - n * (EMB_ / 2), k = q * 2;
    float2 v = make_float2(0.f, 0.f);
    if (n < G4_) {
        int j = n >> 2, g = n & 3;
        v = *(const float2*)&src[(size_t)(g * HID_ + j) * EMB_ + k];
    }
    unsigned o = ((unsigned)bfc(v.y) << 16) | (unsigned)bfc(v.x);
    *(unsigned*)&g_Wxb[slot][n * EMB_ + k] = o;
}

// ---------------- embedding gather -> bf16 ----------------
__global__ __launch_bounds__(256) void gather_x(const int* __restrict__ x,
                                                const int* __restrict__ y,
                                                const float* __restrict__ encemb,
                                                const float* __restrict__ decemb)
{
    const int row = blockIdx.x;           // 0..2047 (= t*32+b)
    const int which = blockIdx.y;
    const int tok = which ? y[row] : x[row];
    const float* emb = which ? decemb : encemb;
    const int k = threadIdx.x;            // 256
    g_xb[which][row * EMB_ + k] = __float2bfloat16(emb[(size_t)tok * EMB_ + k]);
}

// ---------------- input projection GEMM: pre = xb @ Wih0^T + bias (bf16 mma) ----------------
__global__ __launch_bounds__(256) void pre_gemm() {
    extern __shared__ __align__(16) unsigned short psm[];
    unsigned short* sA = psm;                       // [128][XROW_]
    unsigned short* sB = psm + 128 * XROW_;         // [64][XROW_]
    const int tid = threadIdx.x, lane = tid & 31, warp = tid >> 5;
    const int which = blockIdx.y >> 4, mtile = blockIdx.y & 15;
    const int m0 = mtile * 128, n0 = blockIdx.x * 64;

    {
        const uint2* srcA = (const uint2*)(g_xb[which] + (size_t)m0 * EMB_);
        uint2* dA = (uint2*)sA;
        int r = tid >> 1;
        #pragma unroll
        for (int k = (tid & 1); k < 64; k += 2) dA[r * (XROW_ / 4) + k] = srcA[r * 64 + k];
        const uint2* srcB = (const uint2*)(g_Wxb[which] + (size_t)n0 * EMB_);
        uint2* dB = (uint2*)sB;
        int rb = tid >> 2;
        #pragma unroll
        for (int k = (tid & 3); k < 64; k += 4) dB[rb * (XROW_ / 4) + k] = srcB[rb * 64 + k];
    }
    __syncthreads();

    const int wm = warp >> 2, wn = warp & 3;   // 2 x 4
    float acc[4][2][4];
    #pragma unroll
    for (int a = 0; a < 4; a++) for (int b = 0; b < 2; b++) for (int r = 0; r < 4; r++)
        acc[a][b][r] = 0.f;

    const unsigned sbA = smem_u32(sA);
    const unsigned a_off =
        (((unsigned)((lane & 7) + ((lane >> 3) & 1) * 8)) * XROW_ + (unsigned)(lane >> 4) * 8) * 2;
    const unsigned short* brow = sB + (wn * 16 + (lane >> 2)) * XROW_ + (lane & 3) * 2;

    #pragma unroll 4
    for (int ki = 0; ki < 16; ki++) {
        const int k0 = ki * 16;
        unsigned av[4][4];
        #pragma unroll
        for (int mt = 0; mt < 4; mt++)
            ldsm4(av[mt], sbA + a_off + (unsigned)((wm * 64 + mt * 16) * XROW_ + k0) * 2);
        #pragma unroll
        for (int nt = 0; nt < 2; nt++) {
            unsigned b0 = *(const unsigned*)(brow + nt * 8 * XROW_ + k0);
            unsigned b1 = *(const unsigned*)(brow + nt * 8 * XROW_ + k0 + 8);
            #pragma unroll
            for (int mt = 0; mt < 4; mt++) mma_bf16(acc[mt][nt], av[mt], b0, b1);
        }
    }

    float ex[4][2][4];
    #pragma unroll
    for (int a = 0; a < 4; a++) for (int b = 0; b < 2; b++) for (int r = 0; r < 4; r++)
        ex[a][b][r] = __shfl_xor_sync(0xffffffffu, acc[a][b][r], 1);

    if (!(lane & 1)) {
        #pragma unroll
        for (int mt = 0; mt < 4; mt++) {
            #pragma unroll
            for (int nt = 0; nt < 2; nt++) {
                const int cn = n0 + wn * 16 + nt * 8 + (lane & 3) * 2;
                if (cn >= G4_) continue;
                const float4 bi = *(const float4*)&g_biasI0[which][cn];
                #pragma unroll
                for (int half = 0; half < 2; half++) {
                    const int row = m0 + wm * 64 + mt * 16 + half * 8 + (lane >> 2);
                    float4 o4;
                    o4.x = acc[mt][nt][half * 2 + 0] + bi.x;
                    o4.y = acc[mt][nt][half * 2 + 1] + bi.y;
                    o4.z = ex[mt][nt][half * 2 + 0] + bi.z;
                    o4.w = ex[mt][nt][half * 2 + 1] + bi.w;
                    *(float4*)&g_pre[which][(size_t)row * G4_ + cn] = o4;
                }
            }
        }
    }
}

// ---------------- persistent scan: 132 blocks, resident weights, cheap barrier ----------------
__device__ __forceinline__ void gbar(int s) {
    __syncthreads();
    if (threadIdx.x == 0) {
        asm volatile("red.release.gpu.global.add.u32 [%0], %1;"
            :: "l"(&g_cnt), "r"(1u) : "memory");
        const unsigned target = (unsigned)SCANB_ * (unsigned)(s + 1);
        unsigned v;
        do {
            asm volatile("ld.acquire.gpu.global.u32 %0, [%1];"
                : "=r"(v) : "l"(&g_cnt) : "memory");
        } while (v < target);
    }
    __syncthreads();
}

// copy 32 rows x 528 u16 (256 threads): FULL row = 66 uint4 (1056B),
// src row stride 66 uint4 (NK_), dst row stride 67 uint4 (SROW_).
__device__ __forceinline__ void copy32w(const void* src, unsigned short* dst, int tid) {
    const uint4* s = (const uint4*)src;
    uint4* d = (uint4*)dst;
    const int r = tid >> 3;               // 32 rows, 8 threads each
    #pragma unroll
    for (int k = (tid & 7); k < 66; k += 8)
        d[r * (SROW_ / 8) + k] = s[r * 66 + k];
}

// warp-tile GEMM: one m16n8 over K=528, TWO accumulator chains (even/odd ki).
__device__ __forceinline__ void gemm_w2(const unsigned short* wrow, unsigned abase,
                                        float acc0[4], float acc1[4]) {
    #pragma unroll 4
    for (int kp = 0; kp < 16; kp++) {                // pairs: ki = 2kp, 2kp+1
        const int k0 = kp * 32;
        unsigned av0[4], av1[4];
        ldsm4(av0, abase + (unsigned)k0 * 2);
        ldsm4(av1, abase + (unsigned)(k0 + 16) * 2);
        unsigned b00 = *(const unsigned*)(wrow + k0);
        unsigned b01 = *(const unsigned*)(wrow + k0 + 8);
        unsigned b10 = *(const unsigned*)(wrow + k0 + 16);
        unsigned b11 = *(const unsigned*)(wrow + k0 + 24);
        mma_bf16(acc0, av0, b00, b01);
        mma_bf16(acc1, av1, b10, b11);
    }
    {   // tail ki = 32
        const int k0 = 512;
        unsigned av[4];
        ldsm4(av, abase + (unsigned)k0 * 2);
        unsigned b0 = *(const unsigned*)(wrow + k0);
        unsigned b1 = *(const unsigned*)(wrow + k0 + 8);
        mma_bf16(acc0, av, b0, b1);
    }
}

// 132 blocks x 256 threads. bid<66: layer0 tile; bid>=66: layer1 tile (32 gate-cols).
// 8 warps: warp = mt(0..1) x nt(0..3): m16 x n8 warp-tile.
__global__ __launch_bounds__(256) void scan_kernel() {
    extern __shared__ __align__(16) unsigned short ssm[];
    unsigned short* sA0 = ssm;                  // h0(s-1)  [32][SROW_]
    unsigned short* sA1 = ssm + 32 * SROW_;     // h1(s-2)  (layer1 only)
    unsigned short* sWa = ssm + 2 * 32 * SROW_; // layer0: Whh0 | layer1: Wih1
    unsigned short* sWb = ssm + 3 * 32 * SROW_; // layer1: Whh1
    const int bid = blockIdx.x;
    const int layer = (bid >= 66) ? 1 : 0;
    const int tile = layer ? bid - 66 : bid;
    const int tid = threadIdx.x, lane = tid & 31, warp = tid >> 5;
    const int mt = warp >> 2, nt = warp & 3;
    const int m_off = mt * 16;
    const int nw = tile * 32 + nt * 8;
    const int cn = nw + (lane & 3) * 2;
    const int j = cn >> 2;
    const size_t woff = (size_t)tile * 32 * NK_;

    const unsigned a_off =
        (((unsigned)((lane & 7) + ((lane >> 3) & 1) * 8)) * SROW_ + (unsigned)(lane >> 4) * 8) * 2;
    const unsigned a0base = smem_u32(sA0) + (unsigned)m_off * SROW_ * 2 + a_off;
    const unsigned a1base = smem_u32(sA1) + (unsigned)m_off * SROW_ * 2 + a_off;
    const unsigned short* wrowA = sWa + (nt * 8 + (lane >> 2)) * SROW_ + (lane & 3) * 2;
    const unsigned short* wrowB = sWb + (nt * 8 + (lane >> 2)) * SROW_ + (lane & 3) * 2;

    for (int s = 0; s <= 128; s++) {
        // weight phase loads
        if (layer == 0) {
            if (s == 0)  copy32w(g_Wb[0] + woff, sWa, tid);
            if (s == 64) copy32w(g_Wb[3] + woff, sWa, tid);
        } else {
            if (s == 0)  { copy32w(g_Wb[1] + woff, sWa, tid); copy32w(g_Wb[2] + woff, sWb, tid); }
            if (s == 65) { copy32w(g_Wb[4] + woff, sWa, tid); copy32w(g_Wb[5] + woff, sWb, tid); }
        }
        // h staging
        copy32w(g_hb[0][(s & 1) ^ 1], sA0, tid);           // h0(s-1)
        if (layer) copy32w(g_hb[1][s & 1], sA1, tid);      // h1(s-2)
        __syncthreads();

        const bool active = layer ? (s >= 1) : (s <= 127);
        if (active) {
            float acc[4];
            if (layer) {
                float pa0[4] = {0,0,0,0}, pa1[4] = {0,0,0,0};
                float pb0[4] = {0,0,0,0}, pb1[4] = {0,0,0,0};
                gemm_w2(wrowA, a0base, pa0, pa1);   // Wih1 @ h0(s-1)
                gemm_w2(wrowB, a1base, pb0, pb1);   // Whh1 @ h1(s-2)
                #pragma unroll
                for (int r = 0; r < 4; r++)
                    acc[r] = (pa0[r] + pa1[r]) + (pb0[r] + pb1[r]);
            } else {
                float p0[4] = {0,0,0,0}, p1[4] = {0,0,0,0};
                gemm_w2(wrowA, a0base, p0, p1);     // Whh0 @ h0(s-1)
                #pragma unroll
                for (int r = 0; r < 4; r++)
                    acc[r] = p0[r] + p1[r];
            }
            float ex[4];
            #pragma unroll
            for (int r = 0; r < 4; r++)
                ex[r] = __shfl_xor_sync(0xffffffffu, acc[r], 1);

            if (!(lane & 1) && cn < G4_) {
                const int z = s - 1;                      // layer1 step
                const int sel = layer ? (z >= 64 ? 1 : 0) : (s >= 64 ? 1 : 0);
                const int tstep = layer ? (sel ? z - 64 : z) : (sel ? s - 64 : s);
                float* cst = g_c[layer];
                __nv_bfloat16* hout = layer ? g_hb[1][(s & 1) ^ 1] : g_hb[0][s & 1];
                #pragma unroll
                for (int half = 0; half < 2; half++) {
                    const int b = m_off + half * 8 + (lane >> 2);
                    float4 add = layer
                        ? *(const float4*)&g_biasI1[sel][cn]
                        : *(const float4*)&g_pre[sel][(size_t)(tstep * B_ + b) * G4_ + cn];
                    float iv = sigf(acc[half * 2 + 0] + add.x);
                    float fv = sigf(acc[half * 2 + 1] + add.y);
                    float gv = tanhf(ex[half * 2 + 0] + add.z);
                    float ov = sigf(ex[half * 2 + 1] + add.w);
                    float c = cst[b * HID_ + j];
                    c = fv * c + iv * gv;
                    cst[b * HID_ + j] = c;
                    float h = ov * tanhf(c);
                    __nv_bfloat16 hb = __float2bfloat16(h);
                    hout[b * NK_ + j] = hb;
                    if (layer && sel) g_histb[(size_t)(tstep * B_ + b) * NK_ + j] = hb;
                }
            }
        }
        if (s < 128) gbar(s);
    }
}

// ---------------- fused vocab projection + CE: Wout read once, M-loop inside ----------------
// grid 250 blocks x 256 thr. Block owns 128-vocab N-tile resident in smem (fp32->bf16
// converted in-kernel), loops 16 M-tiles with double-buffered 64-wide cp.async A chunks.
__global__ __launch_bounds__(256) void ce2(const float* __restrict__ Wout,
                                           const float* __restrict__ bout,
                                           const int* __restrict__ y) {
    extern __shared__ __align__(16) unsigned short csm[];
    unsigned short* sB = csm;                       // [128][SROW_] bf16 Wout tile
    unsigned short* sA = csm + 128 * SROW_;         // 2 x [128][CROW2_]
    const int tid = threadIdx.x, lane = tid & 31, warp = tid >> 5;
    const int bx = blockIdx.x;

    // ---- load + convert B tile fp32 -> bf16 (once) ----
    {
        const int r = tid >> 1;
        const int n = bx * 128 + r;
        const float4* src = (const float4*)(Wout + (size_t)n * HID_);
        unsigned short* drow = sB + r * SROW_;
        for (int q = (tid & 1); q < 129; q += 2) {
            float4 v = src[q];
            ushort4 o;
            o.x = bfc(v.x); o.y = bfc(v.y); o.z = bfc(v.z); o.w = bfc(v.w);
            *(ushort4*)(drow + q * 4) = o;
        }
        if (tid & 1) {   // zero pad cols 516..527
            ushort4 zz = make_ushort4(0, 0, 0, 0);
            *(ushort4*)(drow + 516) = zz;
            *(ushort4*)(drow + 520) = zz;
            *(ushort4*)(drow + 524) = zz;
        }
    }

    const int wm = warp >> 2, wn = warp & 3;
    const unsigned sbA = smem_u32(sA);
    const unsigned bufB = (unsigned)128 * CROW2_ * 2;
    const unsigned a_off =
        (((unsigned)((lane & 7) + ((lane >> 3) & 1) * 8)) * CROW2_ + (unsigned)(lane >> 4) * 8) * 2;
    const unsigned short* brow = sB + (wn * 32 + (lane >> 2)) * SROW_ + (lane & 3) * 2;

    const int sr = tid >> 1, sh = tid & 1;   // staging: row, half (64B each for c<8)

    // stage chunk c (k = c*64..): 128B/row for c<8 (2 thr x 4x16B), 32B/row for c==8
    #define CSTAGE(MT, C) do { \
        const size_t srcbase = (size_t)((MT) * 128 + sr) * NK_ + (C) * 64; \
        unsigned dstr = smem_u32(sA) + ((unsigned)((C) & 1)) * bufB \
                      + (unsigned)(sr * CROW2_) * 2; \
        if ((C) < 8) { \
            const char* s0 = (const char*)(g_histb + srcbase + sh * 32); \
            unsigned d0 = dstr + (unsigned)(sh * 32) * 2; \
            asm volatile("cp.async.cg.shared.global [%0], [%1], 16;" :: "r"(d0), "l"(s0)); \
            asm volatile("cp.async.cg.shared.global [%0], [%1], 16;" :: "r"(d0 + 16), "l"(s0 + 16)); \
            asm volatile("cp.async.cg.shared.global [%0], [%1], 16;" :: "r"(d0 + 32), "l"(s0 + 32)); \
            asm volatile("cp.async.cg.shared.global [%0], [%1], 16;" :: "r"(d0 + 48), "l"(s0 + 48)); \
        } else { \
            const char* s0 = (const char*)(g_histb + srcbase + sh * 8); \
            unsigned d0 = dstr + (unsigned)(sh * 8) * 2; \
            asm volatile("cp.async.cg.shared.global [%0], [%1], 16;" :: "r"(d0), "l"(s0)); \
        } \
        asm volatile("cp.async.commit_group;"); \
    } while (0)

    __syncthreads();   // sB ready

    for (int mt = 0; mt < 16; mt++) {
        float acc[4][4][4];
        #pragma unroll
        for (int a = 0; a < 4; a++) for (int b = 0; b < 4; b++) for (int r = 0; r < 4; r++)
            acc[a][b][r] = 0.f;

        CSTAGE(mt, 0);
        for (int c = 0; c < 9; c++) {
            if (c + 1 < 9) {
                CSTAGE(mt, c + 1);
                asm volatile("cp.async.wait_group 1;");
            } else {
                asm volatile("cp.async.wait_group 0;");
            }
            __syncthreads();
            const unsigned chbase = sbA + ((unsigned)(c & 1)) * bufB + a_off;
            const int nk16 = (c == 8) ? 1 : 4;
            for (int kk = 0; kk < nk16; kk++) {
                unsigned av[4][4];
                #pragma unroll
                for (int q = 0; q < 4; q++)
                    ldsm4(av[q], chbase + (unsigned)((wm * 64 + q * 16) * CROW2_ + kk * 16) * 2);
                const int k0 = c * 64 + kk * 16;
                #pragma unroll
                for (int nt = 0; nt < 4; nt++) {
                    unsigned b0 = *(const unsigned*)(brow + nt * 8 * SROW_ + k0);
                    unsigned b1 = *(const unsigned*)(brow + nt * 8 * SROW_ + k0 + 8);
                    #pragma unroll
                    for (int q = 0; q < 4; q++) mma_bf16(acc[q][nt], av[q], b0, b1);
                }
            }
            __syncthreads();
        }

        // epilogue for this m-tile
        #pragma unroll
        for (int q = 0; q < 4; q++) {
            const int r0 = mt * 128 + wm * 64 + q * 16 + (lane >> 2);
            const int r1 = r0 + 8;
            const int tg0 = y[r0 + 32];
            const int tg1 = y[r1 + 32];
            float s0 = 0.f, s1 = 0.f;
            #pragma unroll
            for (int nt = 0; nt < 4; nt++) {
                const int cnv = bx * 128 + wn * 32 + nt * 8 + (lane & 3) * 2;
                const float2 bo = *(const float2*)&bout[cnv];
                float l0 = acc[q][nt][0] + bo.x;
                float l1 = acc[q][nt][1] + bo.y;
                float l2 = acc[q][nt][2] + bo.x;
                float l3 = acc[q][nt][3] + bo.y;
                s0 += __expf(l0) + __expf(l1);
                s1 += __expf(l2) + __expf(l3);
                if (cnv == tg0)     atomicAdd(&g_tgt[r0], l0);
                if (cnv + 1 == tg0) atomicAdd(&g_tgt[r0], l1);
                if (cnv == tg1)     atomicAdd(&g_tgt[r1], l2);
                if (cnv + 1 == tg1) atomicAdd(&g_tgt[r1], l3);
            }
            s0 += __shfl_xor_sync(0xffffffffu, s0, 1);
            s0 += __shfl_xor_sync(0xffffffffu, s0, 2);
            s1 += __shfl_xor_sync(0xffffffffu, s1, 1);
            s1 += __shfl_xor_sync(0xffffffffu, s1, 2);
            if (!(lane & 3)) {
                atomicAdd(&g_sumexp[r0], s0);
                atomicAdd(&g_sumexp[r1], s1);
            }
        }
    }
    #undef CSTAGE
}

// ---------------- final reduction ----------------
__global__ __launch_bounds__(256) void finalize_kernel(float* out) {
    __shared__ float sm[256];
    float s = 0.f;
    for (int r = threadIdx.x; r < ROWS_; r += 256)
        s += logf(g_sumexp[r]) - g_tgt[r];
    sm[threadIdx.x] = s;
    __syncthreads();
    for (int st = 128; st; st >>= 1) {
        if (threadIdx.x < st) sm[threadIdx.x] += sm[threadIdx.x + st];
        __syncthreads();
    }
    if (threadIdx.x == 0) out[0] = sm[0] / 32.f;
}

// ---------------- host launcher ----------------
extern "C" void kernel_launch(void* const* d_in, const int* in_sizes, int n_in,
                              void* d_out, int out_size)
{
    (void)in_sizes; (void)n_in; (void)out_size;
    const int*   x        = (const int*)  d_in[0];
    const int*   y        = (const int*)  d_in[1];
    const float* encemb   = (const float*)d_in[2];
    const float* decemb   = (const float*)d_in[3];
    const float* enc_Wih0 = (const float*)d_in[4];
    const float* enc_Whh0 = (const float*)d_in[5];
    const float* enc_bih0 = (const float*)d_in[6];
    const float* enc_bhh0 = (const float*)d_in[7];
    const float* enc_Wih1 = (const float*)d_in[8];
    const float* enc_Whh1 = (const float*)d_in[9];
    const float* enc_bih1 = (const float*)d_in[10];
    const float* enc_bhh1 = (const float*)d_in[11];
    const float* dec_Wih0 = (const float*)d_in[12];
    const float* dec_Whh0 = (const float*)d_in[13];
    const float* dec_bih0 = (const float*)d_in[14];
    const float* dec_bhh0 = (const float*)d_in[15];
    const float* dec_Wih1 = (const float*)d_in[16];
    const float* dec_Whh1 = (const float*)d_in[17];
    const float* dec_bih1 = (const float*)d_in[18];
    const float* dec_bhh1 = (const float*)d_in[19];
    const float* Wout     = (const float*)d_in[20];
    const float* bout     = (const float*)d_in[21];
    float* out = (float*)d_out;

    const int PRE_SMEM  = (128 + 64) * XROW_ * 2;                     // 101,376
    const int SCAN_SMEM = 4 * 32 * SROW_ * 2;                         // 137,216
    const int CE_SMEM   = 128 * SROW_ * 2 + 2 * 128 * CROW2_ * 2;     // 174,080
    cudaFuncSetAttribute(pre_gemm,    cudaFuncAttributeMaxDynamicSharedMemorySize, PRE_SMEM);
    cudaFuncSetAttribute(scan_kernel, cudaFuncAttributeMaxDynamicSharedMemorySize, SCAN_SMEM);
    cudaFuncSetAttribute(ce2,         cudaFuncAttributeMaxDynamicSharedMemorySize, CE_SMEM);

    // launch order fixed so ncu (-s 5 -c 1) samples scan_kernel (6th launch)
    setup_kernel<<<256, 256>>>(enc_bih0, enc_bhh0, dec_bih0, dec_bhh0,     // 0
                               enc_bih1, enc_bhh1, dec_bih1, dec_bhh1);

    Ptrs6 p6;
    p6.p[0] = enc_Whh0; p6.p[1] = enc_Wih1; p6.p[2] = enc_Whh1;
    p6.p[3] = dec_Whh0; p6.p[4] = dec_Wih1; p6.p[5] = dec_Whh1;
    const int GC = (NPAD_ * NK2_ + 255) / 256;
    conv_gate_all<<<dim3(GC, 6), 256>>>(p6);                                // 1

    Ptrs2 p2; p2.p[0] = enc_Wih0; p2.p[1] = dec_Wih0;
    const int GX = (NPAD_ * (EMB_ / 2) + 255) / 256;
    conv_gate_x<<<dim3(GX, 2), 256>>>(p2);                                  // 2

    gather_x<<<dim3(ROWS_, 2), EMB_>>>(x, y, encemb, decemb);               // 3
    pre_gemm<<<dim3(33, 32), 256, PRE_SMEM>>>();                            // 4

    scan_kernel<<<SCANB_, 256, SCAN_SMEM>>>();                              // 5  <- ncu sample

    ce2<<<250, 256, CE_SMEM>>>(Wout, bout, y);                              // 6

    finalize_kernel<<<1, 256>>>(out);                                       // 7
}

// round 10
// speedup vs baseline: 1.0300x; 1.0300x over previous
#include <cuda_runtime.h>
#include <cuda_bf16.h>
#include <math.h>

#define B_    32
#define EMB_  256
#define HID_  516
#define G4_   2064     // 4*HID_
#define V_    32000
#define ROWS_ 2048     // 64*32 decoder rows
#define NK_   528      // K padded to multiple of 16
#define NK2_  264      // NK_/2 (u32 units)
#define NKI_  33       // k-iterations of 16
#define SROW_ 536      // smem row stride (u16), ldmatrix conflict-free; 1072B = 67 uint4
#define XROW_ 264      // smem row stride (u16) for K=256 tiles
#define NPAD_ 2112     // gate-col dim padded (66 tiles * 32)
#define SCANB_ 132     // scan blocks (<=148, all co-resident)
#define CROW2_ 72      // CE A-chunk row stride (u16), 64 cols + pad

// ---------------- scratch (static device globals; no allocation) ----------------
__device__ __nv_bfloat16 g_Wb[6][NPAD_ * NK_];        // scan weights bf16, gate-interleaved [j*4+g][k]
__device__ float         g_pre[2][ROWS_ * G4_];       // input proj + bias, gate-interleaved
__device__ __nv_bfloat16 g_hb[2][2][B_ * NK_];        // h state [layer][buf], bf16 k-padded
__device__ float         g_c[2][B_ * HID_];           // c state fp32
__device__ __nv_bfloat16 g_histb[ROWS_ * NK_ + 64];   // decoder h1 history bf16 (+pad)
__device__ float         g_biasI0[2][G4_];            // layer0 bias (folded into pre)
__device__ float         g_biasI1[2][G4_];            // layer1 bias
__device__ float         g_sumexp[ROWS_];
__device__ float         g_tgt[ROWS_];
__device__ unsigned      g_cnt;                       // grid barrier arrivals (monotonic)

// ---------------- helpers ----------------
__device__ __forceinline__ unsigned smem_u32(const void* p) {
    return (unsigned)__cvta_generic_to_shared(p);
}
__device__ __forceinline__ void ldsm4(unsigned a[4], unsigned addr) {
    asm volatile("ldmatrix.sync.aligned.m8n8.x4.shared.b16 {%0,%1,%2,%3}, [%4];"
        : "=r"(a[0]), "=r"(a[1]), "=r"(a[2]), "=r"(a[3]) : "r"(addr));
}
__device__ __forceinline__ void mma_bf16(float c[4], const unsigned a[4], unsigned b0, unsigned b1) {
    asm volatile("mma.sync.aligned.m16n8k16.row.col.f32.bf16.bf16.f32 "
        "{%0,%1,%2,%3},{%4,%5,%6,%7},{%8,%9},{%0,%1,%2,%3};"
        : "+f"(c[0]), "+f"(c[1]), "+f"(c[2]), "+f"(c[3])
        : "r"(a[0]), "r"(a[1]), "r"(a[2]), "r"(a[3]), "r"(b0), "r"(b1));
}
__device__ __forceinline__ float sigf(float x) {
    return __fdividef(1.f, 1.f + __expf(-x));
}
__device__ __forceinline__ float tanh_f(float x) {
    float t = __expf(2.f * x);
    return __fdividef(t - 1.f, t + 1.f);
}
__device__ __forceinline__ unsigned short bfc(float v) {
    return __bfloat16_as_ushort(__float2bfloat16(v));
}

// ---------------- setup: init state + reduction buffers + fold biases ----------------
__global__ void setup_kernel(
    const float* eb0a, const float* eb0b, const float* db0a, const float* db0b,
    const float* eb1a, const float* eb1b, const float* db1a, const float* db1b)
{
    const int stride = gridDim.x * blockDim.x;
    const int i0 = blockIdx.x * blockDim.x + threadIdx.x;
    const __nv_bfloat16 z = __float2bfloat16(0.f);
    for (int i = i0; i < B_ * NK_; i += stride) {
        g_hb[0][0][i] = z; g_hb[0][1][i] = z;
        g_hb[1][0][i] = z; g_hb[1][1][i] = z;
    }
    for (int i = i0; i < B_ * HID_; i += stride) { g_c[0][i] = 0.f; g_c[1][i] = 0.f; }
    for (int i = i0; i < ROWS_; i += stride)     { g_sumexp[i] = 0.f; g_tgt[i] = 0.f; }
    // zero hist pad cols (516..527) so CE mma on pads is 0*0
    for (int i = i0; i < ROWS_ * 12; i += stride) {
        int r = i / 12, k = HID_ + i - r * 12;
        g_histb[r * NK_ + k] = z;
    }
    // fold biases (gate-interleaved)
    for (int t = i0; t < 2 * G4_; t += stride) {
        int sel = t / G4_, n = t - sel * G4_;
        int j = n >> 2, g = n & 3;
        g_biasI0[sel][n] = (sel ? db0a : eb0a)[g * HID_ + j] + (sel ? db0b : eb0b)[g * HID_ + j];
        g_biasI1[sel][n] = (sel ? db1a : eb1a)[g * HID_ + j] + (sel ? db1b : eb1b)[g * HID_ + j];
    }
    if (blockIdx.x == 0 && threadIdx.x == 0) g_cnt = 0u;
}

// ---------------- scan weight conversion ----------------
struct Ptrs6 { const float* p[6]; };

__global__ __launch_bounds__(256) void conv_gate_all(Ptrs6 ps) {
    const int slot = blockIdx.y;
    const float* __restrict__ src = ps.p[slot];
    int idx = blockIdx.x * blockDim.x + threadIdx.x;   // over NPAD_*264 (u32 pairs)
    if (idx >= NPAD_ * NK2_) return;
    int n = idx / NK2_, q = idx - n * NK2_, k = q * 2;
    float2 v = make_float2(0.f, 0.f);
    if (n < G4_ && k < HID_) {
        int j = n >> 2, g = n & 3;
        v = *(const float2*)&src[(size_t)(g * HID_ + j) * HID_ + k];
    }
    unsigned o = ((unsigned)bfc(v.y) << 16) | (unsigned)bfc(v.x);
    *(unsigned*)&g_Wb[slot][n * NK_ + k] = o;
}

// ---------------- fused input projection: gather + convert + GEMM + bias ----------------
// grid (33, 32): bx = N-tile of 64; by: which = by>>4, mtile = by&15 (M=128 rows).
__global__ __launch_bounds__(256) void pre_gemm(
    const int* __restrict__ x, const int* __restrict__ y,
    const float* __restrict__ encemb, const float* __restrict__ decemb,
    const float* __restrict__ Wih0e, const float* __restrict__ Wih0d)
{
    extern __shared__ __align__(16) unsigned short psm[];
    unsigned short* sA = psm;                       // [128][XROW_] embeddings bf16
    unsigned short* sB = psm + 128 * XROW_;         // [64][XROW_]  Wih0 gate-interleaved bf16
    const int tid = threadIdx.x, lane = tid & 31, warp = tid >> 5;
    const int which = blockIdx.y >> 4, mtile = blockIdx.y & 15;
    const int m0 = mtile * 128, n0 = blockIdx.x * 64;
    const int* idx = which ? y : x;
    const float* emb = which ? decemb : encemb;
    const float* Wsrc = which ? Wih0d : Wih0e;

    // ---- stage A: gather 128 embedding rows, fp32 -> bf16 ----
    {
        const int r = tid >> 1, h = tid & 1;        // row, col-half (128 floats)
        const int tok = idx[m0 + r];
        const float4* es = (const float4*)(emb + (size_t)tok * EMB_ + h * 128);
        unsigned short* drow = sA + r * XROW_ + h * 128;
        #pragma unroll
        for (int q = 0; q < 32; q++) {
            float4 v = es[q];
            ushort4 o;
            o.x = bfc(v.x); o.y = bfc(v.y); o.z = bfc(v.z); o.w = bfc(v.w);
            *(ushort4*)(drow + q * 4) = o;
        }
    }
    // ---- stage B: gate-interleave + convert 64 Wih0 rows ----
    {
        const int rb = tid >> 2, qt = tid & 3;      // row, col-quarter (64 floats)
        const int n = n0 + rb;
        unsigned short* drow = sB + rb * XROW_ + qt * 64;
        if (n < G4_) {
            const int j = n >> 2, g = n & 3;
            const float4* ws = (const float4*)(Wsrc + (size_t)(g * HID_ + j) * EMB_ + qt * 64);
            #pragma unroll
            for (int q = 0; q < 16; q++) {
                float4 v = ws[q];
                ushort4 o;
                o.x = bfc(v.x); o.y = bfc(v.y); o.z = bfc(v.z); o.w = bfc(v.w);
                *(ushort4*)(drow + q * 4) = o;
            }
        } else {
            ushort4 zz = make_ushort4(0, 0, 0, 0);
            #pragma unroll
            for (int q = 0; q < 16; q++) *(ushort4*)(drow + q * 4) = zz;
        }
    }
    __syncthreads();

    const int wm = warp >> 2, wn = warp & 3;   // 2 x 4
    float acc[4][2][4];
    #pragma unroll
    for (int a = 0; a < 4; a++) for (int b = 0; b < 2; b++) for (int r = 0; r < 4; r++)
        acc[a][b][r] = 0.f;

    const unsigned sbA = smem_u32(sA);
    const unsigned a_off =
        (((unsigned)((lane & 7) + ((lane >> 3) & 1) * 8)) * XROW_ + (unsigned)(lane >> 4) * 8) * 2;
    const unsigned short* brow = sB + (wn * 16 + (lane >> 2)) * XROW_ + (lane & 3) * 2;

    #pragma unroll 4
    for (int ki = 0; ki < 16; ki++) {
        const int k0 = ki * 16;
        unsigned av[4][4];
        #pragma unroll
        for (int mt = 0; mt < 4; mt++)
            ldsm4(av[mt], sbA + a_off + (unsigned)((wm * 64 + mt * 16) * XROW_ + k0) * 2);
        #pragma unroll
        for (int nt = 0; nt < 2; nt++) {
            unsigned b0 = *(const unsigned*)(brow + nt * 8 * XROW_ + k0);
            unsigned b1 = *(const unsigned*)(brow + nt * 8 * XROW_ + k0 + 8);
            #pragma unroll
            for (int mt = 0; mt < 4; mt++) mma_bf16(acc[mt][nt], av[mt], b0, b1);
        }
    }

    float ex[4][2][4];
    #pragma unroll
    for (int a = 0; a < 4; a++) for (int b = 0; b < 2; b++) for (int r = 0; r < 4; r++)
        ex[a][b][r] = __shfl_xor_sync(0xffffffffu, acc[a][b][r], 1);

    if (!(lane & 1)) {
        #pragma unroll
        for (int mt = 0; mt < 4; mt++) {
            #pragma unroll
            for (int nt = 0; nt < 2; nt++) {
                const int cn = n0 + wn * 16 + nt * 8 + (lane & 3) * 2;
                if (cn >= G4_) continue;
                const float4 bi = *(const float4*)&g_biasI0[which][cn];
                #pragma unroll
                for (int half = 0; half < 2; half++) {
                    const int row = m0 + wm * 64 + mt * 16 + half * 8 + (lane >> 2);
                    float4 o4;
                    o4.x = acc[mt][nt][half * 2 + 0] + bi.x;
                    o4.y = acc[mt][nt][half * 2 + 1] + bi.y;
                    o4.z = ex[mt][nt][half * 2 + 0] + bi.z;
                    o4.w = ex[mt][nt][half * 2 + 1] + bi.w;
                    *(float4*)&g_pre[which][(size_t)row * G4_ + cn] = o4;
                }
            }
        }
    }
}

// ---------------- persistent scan: 132 blocks, resident weights, cheap barrier ----------------
__device__ __forceinline__ void gbar(int s) {
    __syncthreads();
    if (threadIdx.x == 0) {
        asm volatile("red.release.gpu.global.add.u32 [%0], %1;"
            :: "l"(&g_cnt), "r"(1u) : "memory");
        const unsigned target = (unsigned)SCANB_ * (unsigned)(s + 1);
        unsigned v;
        do {
            asm volatile("ld.acquire.gpu.global.u32 %0, [%1];"
                : "=r"(v) : "l"(&g_cnt) : "memory");
        } while (v < target);
    }
    __syncthreads();
}

// copy 32 rows x 528 u16 (256 threads): FULL row = 66 uint4 (1056B),
// src row stride 66 uint4 (NK_), dst row stride 67 uint4 (SROW_).
__device__ __forceinline__ void copy32w(const void* src, unsigned short* dst, int tid) {
    const uint4* s = (const uint4*)src;
    uint4* d = (uint4*)dst;
    const int r = tid >> 3;               // 32 rows, 8 threads each
    #pragma unroll
    for (int k = (tid & 7); k < 66; k += 8)
        d[r * (SROW_ / 8) + k] = s[r * 66 + k];
}

// warp-tile GEMM: one m16n8 over K=528, single accumulator chain.
__device__ __forceinline__ void gemm_w(const unsigned short* wrow, unsigned abase,
                                       float acc[4]) {
    #pragma unroll 4
    for (int ki = 0; ki < NKI_; ki++) {
        const int k0 = ki * 16;
        unsigned av[4];
        ldsm4(av, abase + (unsigned)k0 * 2);
        unsigned b0 = *(const unsigned*)(wrow + k0);
        unsigned b1 = *(const unsigned*)(wrow + k0 + 8);
        mma_bf16(acc, av, b0, b1);
    }
}

// 132 blocks x 256 threads. bid<66: layer0 tile; bid>=66: layer1 tile (32 gate-cols).
// 8 warps: warp = mt(0..1) x nt(0..3): m16 x n8 warp-tile.
__global__ __launch_bounds__(256) void scan_kernel() {
    extern __shared__ __align__(16) unsigned short ssm[];
    unsigned short* sA0 = ssm;                  // h0(s-1)  [32][SROW_]
    unsigned short* sA1 = ssm + 32 * SROW_;     // h1(s-2)  (layer1 only)
    unsigned short* sWa = ssm + 2 * 32 * SROW_; // layer0: Whh0 | layer1: Wih1
    unsigned short* sWb = ssm + 3 * 32 * SROW_; // layer1: Whh1
    const int bid = blockIdx.x;
    const int layer = (bid >= 66) ? 1 : 0;
    const int tile = layer ? bid - 66 : bid;
    const int tid = threadIdx.x, lane = tid & 31, warp = tid >> 5;
    const int mt = warp >> 2, nt = warp & 3;
    const int m_off = mt * 16;
    const int nw = tile * 32 + nt * 8;
    const int cn = nw + (lane & 3) * 2;
    const int j = cn >> 2;
    const size_t woff = (size_t)tile * 32 * NK_;

    const unsigned a_off =
        (((unsigned)((lane & 7) + ((lane >> 3) & 1) * 8)) * SROW_ + (unsigned)(lane >> 4) * 8) * 2;
    const unsigned a0base = smem_u32(sA0) + (unsigned)m_off * SROW_ * 2 + a_off;
    const unsigned a1base = smem_u32(sA1) + (unsigned)m_off * SROW_ * 2 + a_off;
    const unsigned short* wrowA = sWa + (nt * 8 + (lane >> 2)) * SROW_ + (lane & 3) * 2;
    const unsigned short* wrowB = sWb + (nt * 8 + (lane >> 2)) * SROW_ + (lane & 3) * 2;

    for (int s = 0; s <= 128; s++) {
        // weight phase loads
        if (layer == 0) {
            if (s == 0)  copy32w(g_Wb[0] + woff, sWa, tid);
            if (s == 64) copy32w(g_Wb[3] + woff, sWa, tid);
        } else {
            if (s == 0)  { copy32w(g_Wb[1] + woff, sWa, tid); copy32w(g_Wb[2] + woff, sWb, tid); }
            if (s == 65) { copy32w(g_Wb[4] + woff, sWa, tid); copy32w(g_Wb[5] + woff, sWb, tid); }
        }
        // h staging
        copy32w(g_hb[0][(s & 1) ^ 1], sA0, tid);           // h0(s-1)
        if (layer) copy32w(g_hb[1][s & 1], sA1, tid);      // h1(s-2)
        __syncthreads();

        const bool active = layer ? (s >= 1) : (s <= 127);
        if (active) {
            float acc[4] = {0.f, 0.f, 0.f, 0.f};
            if (layer) {
                gemm_w(wrowA, a0base, acc);   // Wih1 @ h0(s-1)
                gemm_w(wrowB, a1base, acc);   // Whh1 @ h1(s-2)
            } else {
                gemm_w(wrowA, a0base, acc);   // Whh0 @ h0(s-1)
            }
            float ex[4];
            #pragma unroll
            for (int r = 0; r < 4; r++)
                ex[r] = __shfl_xor_sync(0xffffffffu, acc[r], 1);

            if (!(lane & 1) && cn < G4_) {
                const int z = s - 1;                      // layer1 step
                const int sel = layer ? (z >= 64 ? 1 : 0) : (s >= 64 ? 1 : 0);
                const int tstep = layer ? (sel ? z - 64 : z) : (sel ? s - 64 : s);
                float* cst = g_c[layer];
                __nv_bfloat16* hout = layer ? g_hb[1][(s & 1) ^ 1] : g_hb[0][s & 1];
                #pragma unroll
                for (int half = 0; half < 2; half++) {
                    const int b = m_off + half * 8 + (lane >> 2);
                    float4 add = layer
                        ? *(const float4*)&g_biasI1[sel][cn]
                        : *(const float4*)&g_pre[sel][(size_t)(tstep * B_ + b) * G4_ + cn];
                    float iv = sigf(acc[half * 2 + 0] + add.x);
                    float fv = sigf(acc[half * 2 + 1] + add.y);
                    float gv = tanh_f(ex[half * 2 + 0] + add.z);
                    float ov = sigf(ex[half * 2 + 1] + add.w);
                    float c = cst[b * HID_ + j];
                    c = fv * c + iv * gv;
                    cst[b * HID_ + j] = c;
                    float h = ov * tanh_f(c);
                    __nv_bfloat16 hb = __float2bfloat16(h);
                    hout[b * NK_ + j] = hb;
                    if (layer && sel) g_histb[(size_t)(tstep * B_ + b) * NK_ + j] = hb;
                }
            }
        }
        if (s < 128) gbar(s);
    }
}

// ---------------- fused vocab projection + CE: Wout read once, M-loop inside ----------------
// grid 250 blocks x 256 thr. Block owns 128-vocab N-tile resident in smem (fp32->bf16
// converted in-kernel), loops 16 M-tiles with double-buffered 64-wide cp.async A chunks.
__global__ __launch_bounds__(256) void ce2(const float* __restrict__ Wout,
                                           const float* __restrict__ bout,
                                           const int* __restrict__ y) {
    extern __shared__ __align__(16) unsigned short csm[];
    unsigned short* sB = csm;                       // [128][SROW_] bf16 Wout tile
    unsigned short* sA = csm + 128 * SROW_;         // 2 x [128][CROW2_]
    const int tid = threadIdx.x, lane = tid & 31, warp = tid >> 5;
    const int bx = blockIdx.x;

    // ---- load + convert B tile fp32 -> bf16 (once) ----
    {
        const int r = tid >> 1;
        const int n = bx * 128 + r;
        const float4* src = (const float4*)(Wout + (size_t)n * HID_);
        unsigned short* drow = sB + r * SROW_;
        for (int q = (tid & 1); q < 129; q += 2) {
            float4 v = src[q];
            ushort4 o;
            o.x = bfc(v.x); o.y = bfc(v.y); o.z = bfc(v.z); o.w = bfc(v.w);
            *(ushort4*)(drow + q * 4) = o;
        }
        if (tid & 1) {   // zero pad cols 516..527
            ushort4 zz = make_ushort4(0, 0, 0, 0);
            *(ushort4*)(drow + 516) = zz;
            *(ushort4*)(drow + 520) = zz;
            *(ushort4*)(drow + 524) = zz;
        }
    }

    const int wm = warp >> 2, wn = warp & 3;
    const unsigned sbA = smem_u32(sA);
    const unsigned bufB = (unsigned)128 * CROW2_ * 2;
    const unsigned a_off =
        (((unsigned)((lane & 7) + ((lane >> 3) & 1) * 8)) * CROW2_ + (unsigned)(lane >> 4) * 8) * 2;
    const unsigned short* brow = sB + (wn * 32 + (lane >> 2)) * SROW_ + (lane & 3) * 2;

    const int sr = tid >> 1, sh = tid & 1;   // staging: row, half (64B each for c<8)

    // stage chunk c (k = c*64..): 128B/row for c<8 (2 thr x 4x16B), 32B/row for c==8
    #define CSTAGE(MT, C) do { \
        const size_t srcbase = (size_t)((MT) * 128 + sr) * NK_ + (C) * 64; \
        unsigned dstr = smem_u32(sA) + ((unsigned)((C) & 1)) * bufB \
                      + (unsigned)(sr * CROW2_) * 2; \
        if ((C) < 8) { \
            const char* s0 = (const char*)(g_histb + srcbase + sh * 32); \
            unsigned d0 = dstr + (unsigned)(sh * 32) * 2; \
            asm volatile("cp.async.cg.shared.global [%0], [%1], 16;" :: "r"(d0), "l"(s0)); \
            asm volatile("cp.async.cg.shared.global [%0], [%1], 16;" :: "r"(d0 + 16), "l"(s0 + 16)); \
            asm volatile("cp.async.cg.shared.global [%0], [%1], 16;" :: "r"(d0 + 32), "l"(s0 + 32)); \
            asm volatile("cp.async.cg.shared.global [%0], [%1], 16;" :: "r"(d0 + 48), "l"(s0 + 48)); \
        } else { \
            const char* s0 = (const char*)(g_histb + srcbase + sh * 8); \
            unsigned d0 = dstr + (unsigned)(sh * 8) * 2; \
            asm volatile("cp.async.cg.shared.global [%0], [%1], 16;" :: "r"(d0), "l"(s0)); \
        } \
        asm volatile("cp.async.commit_group;"); \
    } while (0)

    __syncthreads();   // sB ready

    for (int mt = 0; mt < 16; mt++) {
        float acc[4][4][4];
        #pragma unroll
        for (int a = 0; a < 4; a++) for (int b = 0; b < 4; b++) for (int r = 0; r < 4; r++)
            acc[a][b][r] = 0.f;

        CSTAGE(mt, 0);
        for (int c = 0; c < 9; c++) {
            if (c + 1 < 9) {
                CSTAGE(mt, c + 1);
                asm volatile("cp.async.wait_group 1;");
            } else {
                asm volatile("cp.async.wait_group 0;");
            }
            __syncthreads();
            const unsigned chbase = sbA + ((unsigned)(c & 1)) * bufB + a_off;
            const int nk16 = (c == 8) ? 1 : 4;
            for (int kk = 0; kk < nk16; kk++) {
                unsigned av[4][4];
                #pragma unroll
                for (int q = 0; q < 4; q++)
                    ldsm4(av[q], chbase + (unsigned)((wm * 64 + q * 16) * CROW2_ + kk * 16) * 2);
                const int k0 = c * 64 + kk * 16;
                #pragma unroll
                for (int nt = 0; nt < 4; nt++) {
                    unsigned b0 = *(const unsigned*)(brow + nt * 8 * SROW_ + k0);
                    unsigned b1 = *(const unsigned*)(brow + nt * 8 * SROW_ + k0 + 8);
                    #pragma unroll
                    for (int q = 0; q < 4; q++) mma_bf16(acc[q][nt], av[q], b0, b1);
                }
            }
            __syncthreads();
        }

        // epilogue for this m-tile
        #pragma unroll
        for (int q = 0; q < 4; q++) {
            const int r0 = mt * 128 + wm * 64 + q * 16 + (lane >> 2);
            const int r1 = r0 + 8;
            const int tg0 = y[r0 + 32];
            const int tg1 = y[r1 + 32];
            float s0 = 0.f, s1 = 0.f;
            #pragma unroll
            for (int nt = 0; nt < 4; nt++) {
                const int cnv = bx * 128 + wn * 32 + nt * 8 + (lane & 3) * 2;
                const float2 bo = *(const float2*)&bout[cnv];
                float l0 = acc[q][nt][0] + bo.x;
                float l1 = acc[q][nt][1] + bo.y;
                float l2 = acc[q][nt][2] + bo.x;
                float l3 = acc[q][nt][3] + bo.y;
                s0 += __expf(l0) + __expf(l1);
                s1 += __expf(l2) + __expf(l3);
                if (cnv == tg0)     atomicAdd(&g_tgt[r0], l0);
                if (cnv + 1 == tg0) atomicAdd(&g_tgt[r0], l1);
                if (cnv == tg1)     atomicAdd(&g_tgt[r1], l2);
                if (cnv + 1 == tg1) atomicAdd(&g_tgt[r1], l3);
            }
            s0 += __shfl_xor_sync(0xffffffffu, s0, 1);
            s0 += __shfl_xor_sync(0xffffffffu, s0, 2);
            s1 += __shfl_xor_sync(0xffffffffu, s1, 1);
            s1 += __shfl_xor_sync(0xffffffffu, s1, 2);
            if (!(lane & 3)) {
                atomicAdd(&g_sumexp[r0], s0);
                atomicAdd(&g_sumexp[r1], s1);
            }
        }
    }
    #undef CSTAGE
}

// ---------------- final reduction ----------------
__global__ __launch_bounds__(256) void finalize_kernel(float* out) {
    __shared__ float sm[256];
    float s = 0.f;
    for (int r = threadIdx.x; r < ROWS_; r += 256)
        s += logf(g_sumexp[r]) - g_tgt[r];
    sm[threadIdx.x] = s;
    __syncthreads();
    for (int st = 128; st; st >>= 1) {
        if (threadIdx.x < st) sm[threadIdx.x] += sm[threadIdx.x + st];
        __syncthreads();
    }
    if (threadIdx.x == 0) out[0] = sm[0] / 32.f;
}

// ---------------- host launcher ----------------
extern "C" void kernel_launch(void* const* d_in, const int* in_sizes, int n_in,
                              void* d_out, int out_size)
{
    (void)in_sizes; (void)n_in; (void)out_size;
    const int*   x        = (const int*)  d_in[0];
    const int*   y        = (const int*)  d_in[1];
    const float* encemb   = (const float*)d_in[2];
    const float* decemb   = (const float*)d_in[3];
    const float* enc_Wih0 = (const float*)d_in[4];
    const float* enc_Whh0 = (const float*)d_in[5];
    const float* enc_bih0 = (const float*)d_in[6];
    const float* enc_bhh0 = (const float*)d_in[7];
    const float* enc_Wih1 = (const float*)d_in[8];
    const float* enc_Whh1 = (const float*)d_in[9];
    const float* enc_bih1 = (const float*)d_in[10];
    const float* enc_bhh1 = (const float*)d_in[11];
    const float* dec_Wih0 = (const float*)d_in[12];
    const float* dec_Whh0 = (const float*)d_in[13];
    const float* dec_bih0 = (const float*)d_in[14];
    const float* dec_bhh0 = (const float*)d_in[15];
    const float* dec_Wih1 = (const float*)d_in[16];
    const float* dec_Whh1 = (const float*)d_in[17];
    const float* dec_bih1 = (const float*)d_in[18];
    const float* dec_bhh1 = (const float*)d_in[19];
    const float* Wout     = (const float*)d_in[20];
    const float* bout     = (const float*)d_in[21];
    float* out = (float*)d_out;

    const int PRE_SMEM  = (128 + 64) * XROW_ * 2;                     // 101,376
    const int SCAN_SMEM = 4 * 32 * SROW_ * 2;                         // 137,216
    const int CE_SMEM   = 128 * SROW_ * 2 + 2 * 128 * CROW2_ * 2;     // 174,080
    cudaFuncSetAttribute(pre_gemm,    cudaFuncAttributeMaxDynamicSharedMemorySize, PRE_SMEM);
    cudaFuncSetAttribute(scan_kernel, cudaFuncAttributeMaxDynamicSharedMemorySize, SCAN_SMEM);
    cudaFuncSetAttribute(ce2,         cudaFuncAttributeMaxDynamicSharedMemorySize, CE_SMEM);

    // launch order: harness emits 2 launches before ours, so scan (our #3)
    // lands at global #5 where ncu -s 5 -c 1 samples.
    setup_kernel<<<256, 256>>>(enc_bih0, enc_bhh0, dec_bih0, dec_bhh0,      // 0
                               enc_bih1, enc_bhh1, dec_bih1, dec_bhh1);

    Ptrs6 p6;
    p6.p[0] = enc_Whh0; p6.p[1] = enc_Wih1; p6.p[2] = enc_Whh1;
    p6.p[3] = dec_Whh0; p6.p[4] = dec_Wih1; p6.p[5] = dec_Whh1;
    const int GC = (NPAD_ * NK2_ + 255) / 256;
    conv_gate_all<<<dim3(GC, 6), 256>>>(p6);                                 // 1

    pre_gemm<<<dim3(33, 32), 256, PRE_SMEM>>>(x, y, encemb, decemb,          // 2
                                              enc_Wih0, dec_Wih0);

    scan_kernel<<<SCANB_, 256, SCAN_SMEM>>>();                               // 3  <- ncu sample

    ce2<<<250, 256, CE_SMEM>>>(Wout, bout, y);                               // 4

    finalize_kernel<<<1, 256>>>(out);                                        // 5
}

// round 11
// speedup vs baseline: 1.2426x; 1.2063x over previous
#include <cuda_runtime.h>
#include <cuda_bf16.h>
#include <math.h>

#define B_    32
#define EMB_  256
#define HID_  516
#define G4_   2064     // 4*HID_
#define V_    32000
#define ROWS_ 2048     // 64*32 decoder rows
#define NK_   528      // K padded to multiple of 16 (hist layout)
#define NKI_  33       // k-iterations of 16
#define SROW_ 536      // row stride (u16) for h/W tiles, ldmatrix conflict-free
#define XROW_ 264      // smem row stride (u16) for K=256 tiles
#define NPAD_ 2112     // gate-col dim padded (66 tiles * 32)
#define SCANB_ 132     // scan blocks (<=148, all co-resident)
#define CROW2_ 72      // CE A-chunk row stride (u16), 64 cols + pad
#define BUFB_  34304   // one staged buffer: 32*SROW_*2 bytes

// ---------------- scratch (static device globals; no allocation) ----------------
__device__ __nv_bfloat16 g_Wb[6][NPAD_ * SROW_];      // scan weights bf16, PADDED rows
__device__ float         g_pre[2][ROWS_ * G4_];       // input proj + bias, gate-interleaved
__device__ __nv_bfloat16 g_hb[2][2][B_ * SROW_];      // h state [layer][buf], PADDED rows
__device__ __nv_bfloat16 g_histb[ROWS_ * NK_ + 64];   // decoder h1 history bf16 (+pad)
__device__ float         g_biasI0[2][G4_];            // layer0 bias (folded into pre)
__device__ float         g_biasI1[2][G4_];            // layer1 bias
__device__ float         g_sumexp[ROWS_];
__device__ float         g_tgt[ROWS_];
__device__ unsigned      g_cnt;                       // grid barrier arrivals (monotonic)

// ---------------- helpers ----------------
__device__ __forceinline__ unsigned smem_u32(const void* p) {
    return (unsigned)__cvta_generic_to_shared(p);
}
__device__ __forceinline__ void ldsm4(unsigned a[4], unsigned addr) {
    asm volatile("ldmatrix.sync.aligned.m8n8.x4.shared.b16 {%0,%1,%2,%3}, [%4];"
        : "=r"(a[0]), "=r"(a[1]), "=r"(a[2]), "=r"(a[3]) : "r"(addr));
}
__device__ __forceinline__ void mma_bf16(float c[4], const unsigned a[4], unsigned b0, unsigned b1) {
    asm volatile("mma.sync.aligned.m16n8k16.row.col.f32.bf16.bf16.f32 "
        "{%0,%1,%2,%3},{%4,%5,%6,%7},{%8,%9},{%0,%1,%2,%3};"
        : "+f"(c[0]), "+f"(c[1]), "+f"(c[2]), "+f"(c[3])
        : "r"(a[0]), "r"(a[1]), "r"(a[2]), "r"(a[3]), "r"(b0), "r"(b1));
}
__device__ __forceinline__ float sigf(float x) {
    return __fdividef(1.f, 1.f + __expf(-x));
}
__device__ __forceinline__ float tanh_f(float x) {
    float t = __expf(2.f * x);
    return __fdividef(t - 1.f, t + 1.f);
}
__device__ __forceinline__ unsigned short bfc(float v) {
    return __bfloat16_as_ushort(__float2bfloat16(v));
}
__device__ __forceinline__ void bulk_cp(unsigned dst, const void* src, unsigned bytes,
                                        unsigned mbar) {
    asm volatile(
        "cp.async.bulk.shared::cluster.global.mbarrier::complete_tx::bytes [%0], [%1], %2, [%3];"
        :: "r"(dst), "l"(src), "r"(bytes), "r"(mbar) : "memory");
}
__device__ __forceinline__ void mbar_expect_tx(unsigned mbar, unsigned bytes) {
    asm volatile("mbarrier.arrive.expect_tx.shared.b64 _, [%0], %1;"
        :: "r"(mbar), "r"(bytes) : "memory");
}
__device__ __forceinline__ void mbar_wait(unsigned mbar, unsigned parity) {
    unsigned done;
    asm volatile(
        "{\n\t.reg .pred p;\n\t"
        "mbarrier.try_wait.parity.acquire.cta.shared::cta.b64 p, [%1], %2;\n\t"
        "selp.b32 %0, 1, 0, p;\n\t}"
        : "=r"(done) : "r"(mbar), "r"(parity) : "memory");
    while (!done) {
        asm volatile(
            "{\n\t.reg .pred p;\n\t"
            "mbarrier.try_wait.parity.acquire.cta.shared::cta.b64 p, [%1], %2, 0x989680;\n\t"
            "selp.b32 %0, 1, 0, p;\n\t}"
            : "=r"(done) : "r"(mbar), "r"(parity) : "memory");
    }
}

// ---------------- setup: init state + reduction buffers + fold biases ----------------
__global__ void setup_kernel(
    const float* eb0a, const float* eb0b, const float* db0a, const float* db0b,
    const float* eb1a, const float* eb1b, const float* db1a, const float* db1b)
{
    const int stride = gridDim.x * blockDim.x;
    const int i0 = blockIdx.x * blockDim.x + threadIdx.x;
    const __nv_bfloat16 z = __float2bfloat16(0.f);
    for (int i = i0; i < B_ * SROW_; i += stride) {
        g_hb[0][0][i] = z; g_hb[0][1][i] = z;
        g_hb[1][0][i] = z; g_hb[1][1][i] = z;
    }
    for (int i = i0; i < ROWS_; i += stride) { g_sumexp[i] = 0.f; g_tgt[i] = 0.f; }
    // zero hist pad cols (516..527) so CE mma on pads is 0*0
    for (int i = i0; i < ROWS_ * 12; i += stride) {
        int r = i / 12, k = HID_ + i - r * 12;
        g_histb[r * NK_ + k] = z;
    }
    // fold biases (gate-interleaved)
    for (int t = i0; t < 2 * G4_; t += stride) {
        int sel = t / G4_, n = t - sel * G4_;
        int j = n >> 2, g = n & 3;
        g_biasI0[sel][n] = (sel ? db0a : eb0a)[g * HID_ + j] + (sel ? db0b : eb0b)[g * HID_ + j];
        g_biasI1[sel][n] = (sel ? db1a : eb1a)[g * HID_ + j] + (sel ? db1b : eb1b)[g * HID_ + j];
    }
    if (blockIdx.x == 0 && threadIdx.x == 0) g_cnt = 0u;
}

// ---------------- scan weight conversion (to padded SROW_ layout) ----------------
struct Ptrs6 { const float* p[6]; };

__global__ __launch_bounds__(256) void conv_gate_all(Ptrs6 ps) {
    const int slot = blockIdx.y;
    const float* __restrict__ src = ps.p[slot];
    int idx = blockIdx.x * blockDim.x + threadIdx.x;   // over NPAD_*268 (u32 pairs)
    if (idx >= NPAD_ * (SROW_ / 2)) return;
    int n = idx / (SROW_ / 2), q = idx - n * (SROW_ / 2), k = q * 2;
    float2 v = make_float2(0.f, 0.f);
    if (n < G4_ && k < HID_) {
        int j = n >> 2, g = n & 3;
        v = *(const float2*)&src[(size_t)(g * HID_ + j) * HID_ + k];
    }
    unsigned o = ((unsigned)bfc(v.y) << 16) | (unsigned)bfc(v.x);
    *(unsigned*)&g_Wb[slot][n * SROW_ + k] = o;
}

// ---------------- fused input projection: gather + convert + GEMM + bias ----------------
// grid (33, 32): bx = N-tile of 64; by: which = by>>4, mtile = by&15 (M=128 rows).
__global__ __launch_bounds__(256) void pre_gemm(
    const int* __restrict__ x, const int* __restrict__ y,
    const float* __restrict__ encemb, const float* __restrict__ decemb,
    const float* __restrict__ Wih0e, const float* __restrict__ Wih0d)
{
    extern __shared__ __align__(16) unsigned short psm[];
    unsigned short* sA = psm;                       // [128][XROW_] embeddings bf16
    unsigned short* sB = psm + 128 * XROW_;         // [64][XROW_]  Wih0 gate-interleaved bf16
    const int tid = threadIdx.x, lane = tid & 31, warp = tid >> 5;
    const int which = blockIdx.y >> 4, mtile = blockIdx.y & 15;
    const int m0 = mtile * 128, n0 = blockIdx.x * 64;
    const int* idx = which ? y : x;
    const float* emb = which ? decemb : encemb;
    const float* Wsrc = which ? Wih0d : Wih0e;

    // ---- stage A: gather 128 embedding rows, fp32 -> bf16 ----
    {
        const int r = tid >> 1, h = tid & 1;
        const int tok = idx[m0 + r];
        const float4* es = (const float4*)(emb + (size_t)tok * EMB_ + h * 128);
        unsigned short* drow = sA + r * XROW_ + h * 128;
        #pragma unroll
        for (int q = 0; q < 32; q++) {
            float4 v = es[q];
            ushort4 o;
            o.x = bfc(v.x); o.y = bfc(v.y); o.z = bfc(v.z); o.w = bfc(v.w);
            *(ushort4*)(drow + q * 4) = o;
        }
    }
    // ---- stage B: gate-interleave + convert 64 Wih0 rows ----
    {
        const int rb = tid >> 2, qt = tid & 3;
        const int n = n0 + rb;
        unsigned short* drow = sB + rb * XROW_ + qt * 64;
        if (n < G4_) {
            const int j = n >> 2, g = n & 3;
            const float4* ws = (const float4*)(Wsrc + (size_t)(g * HID_ + j) * EMB_ + qt * 64);
            #pragma unroll
            for (int q = 0; q < 16; q++) {
                float4 v = ws[q];
                ushort4 o;
                o.x = bfc(v.x); o.y = bfc(v.y); o.z = bfc(v.z); o.w = bfc(v.w);
                *(ushort4*)(drow + q * 4) = o;
            }
        } else {
            ushort4 zz = make_ushort4(0, 0, 0, 0);
            #pragma unroll
            for (int q = 0; q < 16; q++) *(ushort4*)(drow + q * 4) = zz;
        }
    }
    __syncthreads();

    const int wm = warp >> 2, wn = warp & 3;   // 2 x 4
    float acc[4][2][4];
    #pragma unroll
    for (int a = 0; a < 4; a++) for (int b = 0; b < 2; b++) for (int r = 0; r < 4; r++)
        acc[a][b][r] = 0.f;

    const unsigned sbA = smem_u32(sA);
    const unsigned a_off =
        (((unsigned)((lane & 7) + ((lane >> 3) & 1) * 8)) * XROW_ + (unsigned)(lane >> 4) * 8) * 2;
    const unsigned short* brow = sB + (wn * 16 + (lane >> 2)) * XROW_ + (lane & 3) * 2;

    #pragma unroll 4
    for (int ki = 0; ki < 16; ki++) {
        const int k0 = ki * 16;
        unsigned av[4][4];
        #pragma unroll
        for (int mt = 0; mt < 4; mt++)
            ldsm4(av[mt], sbA + a_off + (unsigned)((wm * 64 + mt * 16) * XROW_ + k0) * 2);
        #pragma unroll
        for (int nt = 0; nt < 2; nt++) {
            unsigned b0 = *(const unsigned*)(brow + nt * 8 * XROW_ + k0);
            unsigned b1 = *(const unsigned*)(brow + nt * 8 * XROW_ + k0 + 8);
            #pragma unroll
            for (int mt = 0; mt < 4; mt++) mma_bf16(acc[mt][nt], av[mt], b0, b1);
        }
    }

    float ex[4][2][4];
    #pragma unroll
    for (int a = 0; a < 4; a++) for (int b = 0; b < 2; b++) for (int r = 0; r < 4; r++)
        ex[a][b][r] = __shfl_xor_sync(0xffffffffu, acc[a][b][r], 1);

    if (!(lane & 1)) {
        #pragma unroll
        for (int mt = 0; mt < 4; mt++) {
            #pragma unroll
            for (int nt = 0; nt < 2; nt++) {
                const int cn = n0 + wn * 16 + nt * 8 + (lane & 3) * 2;
                if (cn >= G4_) continue;
                const float4 bi = *(const float4*)&g_biasI0[which][cn];
                #pragma unroll
                for (int half = 0; half < 2; half++) {
                    const int row = m0 + wm * 64 + mt * 16 + half * 8 + (lane >> 2);
                    float4 o4;
                    o4.x = acc[mt][nt][half * 2 + 0] + bi.x;
                    o4.y = acc[mt][nt][half * 2 + 1] + bi.y;
                    o4.z = ex[mt][nt][half * 2 + 0] + bi.z;
                    o4.w = ex[mt][nt][half * 2 + 1] + bi.w;
                    *(float4*)&g_pre[which][(size_t)row * G4_ + cn] = o4;
                }
            }
        }
    }
}

// ---------------- persistent scan: bulk-copy staging, register c, cheap barrier ----------------
__device__ __forceinline__ void gbar(int s) {
    __syncthreads();
    if (threadIdx.x == 0) {
        asm volatile("red.release.gpu.global.add.u32 [%0], %1;"
            :: "l"(&g_cnt), "r"(1u) : "memory");
        const unsigned target = (unsigned)SCANB_ * (unsigned)(s + 1);
        unsigned v;
        do {
            asm volatile("ld.acquire.gpu.global.u32 %0, [%1];"
                : "=r"(v) : "l"(&g_cnt) : "memory");
        } while (v < target);
    }
    __syncthreads();
}

// warp-tile GEMM: one m16n8 over K=528, single accumulator chain.
__device__ __forceinline__ void gemm_w(const unsigned short* wrow, unsigned abase,
                                       float acc[4]) {
    #pragma unroll 4
    for (int ki = 0; ki < NKI_; ki++) {
        const int k0 = ki * 16;
        unsigned av[4];
        ldsm4(av, abase + (unsigned)k0 * 2);
        unsigned b0 = *(const unsigned*)(wrow + k0);
        unsigned b1 = *(const unsigned*)(wrow + k0 + 8);
        mma_bf16(acc, av, b0, b1);
    }
}

// 132 blocks x 256 threads. bid<66: layer0 tile; bid>=66: layer1 tile (32 gate-cols).
__global__ __launch_bounds__(256) void scan_kernel() {
    extern __shared__ __align__(16) unsigned short ssm[];
    unsigned short* sA0 = ssm;                  // h0(s-1)  [32][SROW_]
    unsigned short* sA1 = ssm + 32 * SROW_;     // h1(s-2)  (layer1 only)
    unsigned short* sWa = ssm + 2 * 32 * SROW_; // layer0: Whh0 | layer1: Wih1
    unsigned short* sWb = ssm + 3 * 32 * SROW_; // layer1: Whh1
    const unsigned sbase = smem_u32(ssm);
    const unsigned mbar  = sbase + 4u * BUFB_;
    const int bid = blockIdx.x;
    const int layer = (bid >= 66) ? 1 : 0;
    const int tile = layer ? bid - 66 : bid;
    const int tid = threadIdx.x, lane = tid & 31, warp = tid >> 5;
    const int mt = warp >> 2, nt = warp & 3;
    const int m_off = mt * 16;
    const int nw = tile * 32 + nt * 8;
    const int cn = nw + (lane & 3) * 2;
    const int j = cn >> 2;
    const bool epi = (!(lane & 1)) && (cn < G4_);
    const int b0r = m_off + (lane >> 2);       // epilogue batch, half 0
    const int b1r = b0r + 8;                   // half 1
    const size_t woff = (size_t)tile * 32 * SROW_;

    if (tid == 0) {
        asm volatile("mbarrier.init.shared.b64 [%0], %1;" :: "r"(mbar), "r"(1u) : "memory");
    }
    __syncthreads();

    const unsigned a_off =
        (((unsigned)((lane & 7) + ((lane >> 3) & 1) * 8)) * SROW_ + (unsigned)(lane >> 4) * 8) * 2;
    const unsigned a0base = sbase + (unsigned)m_off * SROW_ * 2 + a_off;
    const unsigned a1base = sbase + BUFB_ + (unsigned)m_off * SROW_ * 2 + a_off;
    const unsigned short* wrowA = sWa + (nt * 8 + (lane >> 2)) * SROW_ + (lane & 3) * 2;
    const unsigned short* wrowB = sWb + (nt * 8 + (lane >> 2)) * SROW_ + (lane & 3) * 2;

    float creg0 = 0.f, creg1 = 0.f;   // persistent cell state (this thread's (b,j) pair)

    for (int s = 0; s <= 128; s++) {
        // ---- stage via TMA bulk copies (one issuing thread) ----
        if (tid == 0) {
            unsigned tx = BUFB_;                            // sA0 always
            if (layer) tx += BUFB_;                         // sA1
            if (layer == 0 && (s == 0 || s == 64)) tx += BUFB_;
            if (layer == 1 && (s == 0 || s == 65)) tx += 2u * BUFB_;
            mbar_expect_tx(mbar, tx);
            bulk_cp(sbase, g_hb[0][(s & 1) ^ 1], BUFB_, mbar);
            if (layer) bulk_cp(sbase + BUFB_, g_hb[1][s & 1], BUFB_, mbar);
            if (layer == 0) {
                if (s == 0)  bulk_cp(sbase + 2u * BUFB_, g_Wb[0] + woff, BUFB_, mbar);
                if (s == 64) bulk_cp(sbase + 2u * BUFB_, g_Wb[3] + woff, BUFB_, mbar);
            } else {
                if (s == 0) {
                    bulk_cp(sbase + 2u * BUFB_, g_Wb[1] + woff, BUFB_, mbar);
                    bulk_cp(sbase + 3u * BUFB_, g_Wb[2] + woff, BUFB_, mbar);
                }
                if (s == 65) {
                    bulk_cp(sbase + 2u * BUFB_, g_Wb[4] + woff, BUFB_, mbar);
                    bulk_cp(sbase + 3u * BUFB_, g_Wb[5] + woff, BUFB_, mbar);
                }
            }
        }

        const bool active = layer ? (s >= 1) : (s <= 127);
        const int z = s - 1;
        const int sel = layer ? (z >= 64 ? 1 : 0) : (s >= 64 ? 1 : 0);
        const int tstep = layer ? (sel ? z - 64 : z) : (sel ? s - 64 : s);

        // ---- prefetch epilogue adds (independent of staged data) ----
        float4 add0, add1;
        if (active && epi) {
            if (layer) {
                add0 = *(const float4*)&g_biasI1[sel][cn];
                add1 = add0;
            } else {
                add0 = *(const float4*)&g_pre[sel][(size_t)(tstep * B_ + b0r) * G4_ + cn];
                add1 = *(const float4*)&g_pre[sel][(size_t)(tstep * B_ + b1r) * G4_ + cn];
            }
        }

        mbar_wait(mbar, s & 1);

        if (active) {
            float acc[4] = {0.f, 0.f, 0.f, 0.f};
            if (layer) {
                gemm_w(wrowA, a0base, acc);   // Wih1 @ h0(s-1)
                gemm_w(wrowB, a1base, acc);   // Whh1 @ h1(s-2)
            } else {
                gemm_w(wrowA, a0base, acc);   // Whh0 @ h0(s-1)
            }
            float ex[4];
            #pragma unroll
            for (int r = 0; r < 4; r++)
                ex[r] = __shfl_xor_sync(0xffffffffu, acc[r], 1);

            if (epi) {
                __nv_bfloat16* hout = layer ? g_hb[1][(s & 1) ^ 1] : g_hb[0][s & 1];
                // half 0
                {
                    float iv = sigf(acc[0] + add0.x);
                    float fv = sigf(acc[1] + add0.y);
                    float gv = tanh_f(ex[0] + add0.z);
                    float ov = sigf(ex[1] + add0.w);
                    creg0 = fv * creg0 + iv * gv;
                    float h = ov * tanh_f(creg0);
                    __nv_bfloat16 hb = __float2bfloat16(h);
                    hout[b0r * SROW_ + j] = hb;
                    if (layer && sel) g_histb[(size_t)(tstep * B_ + b0r) * NK_ + j] = hb;
                }
                // half 1
                {
                    float iv = sigf(acc[2] + add1.x);
                    float fv = sigf(acc[3] + add1.y);
                    float gv = tanh_f(ex[2] + add1.z);
                    float ov = sigf(ex[3] + add1.w);
                    creg1 = fv * creg1 + iv * gv;
                    float h = ov * tanh_f(creg1);
                    __nv_bfloat16 hb = __float2bfloat16(h);
                    hout[b1r * SROW_ + j] = hb;
                    if (layer && sel) g_histb[(size_t)(tstep * B_ + b1r) * NK_ + j] = hb;
                }
            }
        }
        if (s < 128) gbar(s);
    }
}

// ---------------- fused vocab projection + CE: Wout read once, M-loop inside ----------------
#define SROWCE_ 536
__global__ __launch_bounds__(256) void ce2(const float* __restrict__ Wout,
                                           const float* __restrict__ bout,
                                           const int* __restrict__ y) {
    extern __shared__ __align__(16) unsigned short csm[];
    unsigned short* sB = csm;                       // [128][SROWCE_] bf16 Wout tile
    unsigned short* sA = csm + 128 * SROWCE_;       // 2 x [128][CROW2_]
    const int tid = threadIdx.x, lane = tid & 31, warp = tid >> 5;
    const int bx = blockIdx.x;

    // ---- load + convert B tile fp32 -> bf16 (once) ----
    {
        const int r = tid >> 1;
        const int n = bx * 128 + r;
        const float4* src = (const float4*)(Wout + (size_t)n * HID_);
        unsigned short* drow = sB + r * SROWCE_;
        for (int q = (tid & 1); q < 129; q += 2) {
            float4 v = src[q];
            ushort4 o;
            o.x = bfc(v.x); o.y = bfc(v.y); o.z = bfc(v.z); o.w = bfc(v.w);
            *(ushort4*)(drow + q * 4) = o;
        }
        if (tid & 1) {   // zero pad cols 516..527
            ushort4 zz = make_ushort4(0, 0, 0, 0);
            *(ushort4*)(drow + 516) = zz;
            *(ushort4*)(drow + 520) = zz;
            *(ushort4*)(drow + 524) = zz;
        }
    }

    const int wm = warp >> 2, wn = warp & 3;
    const unsigned sbA = smem_u32(sA);
    const unsigned bufB = (unsigned)128 * CROW2_ * 2;
    const unsigned a_off =
        (((unsigned)((lane & 7) + ((lane >> 3) & 1) * 8)) * CROW2_ + (unsigned)(lane >> 4) * 8) * 2;
    const unsigned short* brow = sB + (wn * 32 + (lane >> 2)) * SROWCE_ + (lane & 3) * 2;

    const int sr = tid >> 1, sh = tid & 1;

    #define CSTAGE(MT, C) do { \
        const size_t srcbase = (size_t)((MT) * 128 + sr) * NK_ + (C) * 64; \
        unsigned dstr = smem_u32(sA) + ((unsigned)((C) & 1)) * bufB \
                      + (unsigned)(sr * CROW2_) * 2; \
        if ((C) < 8) { \
            const char* s0 = (const char*)(g_histb + srcbase + sh * 32); \
            unsigned d0 = dstr + (unsigned)(sh * 32) * 2; \
            asm volatile("cp.async.cg.shared.global [%0], [%1], 16;" :: "r"(d0), "l"(s0)); \
            asm volatile("cp.async.cg.shared.global [%0], [%1], 16;" :: "r"(d0 + 16), "l"(s0 + 16)); \
            asm volatile("cp.async.cg.shared.global [%0], [%1], 16;" :: "r"(d0 + 32), "l"(s0 + 32)); \
            asm volatile("cp.async.cg.shared.global [%0], [%1], 16;" :: "r"(d0 + 48), "l"(s0 + 48)); \
        } else { \
            const char* s0 = (const char*)(g_histb + srcbase + sh * 8); \
            unsigned d0 = dstr + (unsigned)(sh * 8) * 2; \
            asm volatile("cp.async.cg.shared.global [%0], [%1], 16;" :: "r"(d0), "l"(s0)); \
        } \
        asm volatile("cp.async.commit_group;"); \
    } while (0)

    __syncthreads();   // sB ready

    for (int mt = 0; mt < 16; mt++) {
        float acc[4][4][4];
        #pragma unroll
        for (int a = 0; a < 4; a++) for (int b = 0; b < 4; b++) for (int r = 0; r < 4; r++)
            acc[a][b][r] = 0.f;

        CSTAGE(mt, 0);
        for (int c = 0; c < 9; c++) {
            if (c + 1 < 9) {
                CSTAGE(mt, c + 1);
                asm volatile("cp.async.wait_group 1;");
            } else {
                asm volatile("cp.async.wait_group 0;");
            }
            __syncthreads();
            const unsigned chbase = sbA + ((unsigned)(c & 1)) * bufB + a_off;
            const int nk16 = (c == 8) ? 1 : 4;
            for (int kk = 0; kk < nk16; kk++) {
                unsigned av[4][4];
                #pragma unroll
                for (int q = 0; q < 4; q++)
                    ldsm4(av[q], chbase + (unsigned)((wm * 64 + q * 16) * CROW2_ + kk * 16) * 2);
                const int k0 = c * 64 + kk * 16;
                #pragma unroll
                for (int nt = 0; nt < 4; nt++) {
                    unsigned b0 = *(const unsigned*)(brow + nt * 8 * SROWCE_ + k0);
                    unsigned b1 = *(const unsigned*)(brow + nt * 8 * SROWCE_ + k0 + 8);
                    #pragma unroll
                    for (int q = 0; q < 4; q++) mma_bf16(acc[q][nt], av[q], b0, b1);
                }
            }
            __syncthreads();
        }

        // epilogue for this m-tile
        #pragma unroll
        for (int q = 0; q < 4; q++) {
            const int r0 = mt * 128 + wm * 64 + q * 16 + (lane >> 2);
            const int r1 = r0 + 8;
            const int tg0 = y[r0 + 32];
            const int tg1 = y[r1 + 32];
            float s0 = 0.f, s1 = 0.f;
            #pragma unroll
            for (int nt = 0; nt < 4; nt++) {
                const int cnv = bx * 128 + wn * 32 + nt * 8 + (lane & 3) * 2;
                const float2 bo = *(const float2*)&bout[cnv];
                float l0 = acc[q][nt][0] + bo.x;
                float l1 = acc[q][nt][1] + bo.y;
                float l2 = acc[q][nt][2] + bo.x;
                float l3 = acc[q][nt][3] + bo.y;
                s0 += __expf(l0) + __expf(l1);
                s1 += __expf(l2) + __expf(l3);
                if (cnv == tg0)     atomicAdd(&g_tgt[r0], l0);
                if (cnv + 1 == tg0) atomicAdd(&g_tgt[r0], l1);
                if (cnv == tg1)     atomicAdd(&g_tgt[r1], l2);
                if (cnv + 1 == tg1) atomicAdd(&g_tgt[r1], l3);
            }
            s0 += __shfl_xor_sync(0xffffffffu, s0, 1);
            s0 += __shfl_xor_sync(0xffffffffu, s0, 2);
            s1 += __shfl_xor_sync(0xffffffffu, s1, 1);
            s1 += __shfl_xor_sync(0xffffffffu, s1, 2);
            if (!(lane & 3)) {
                atomicAdd(&g_sumexp[r0], s0);
                atomicAdd(&g_sumexp[r1], s1);
            }
        }
    }
    #undef CSTAGE
}

// ---------------- final reduction ----------------
__global__ __launch_bounds__(256) void finalize_kernel(float* out) {
    __shared__ float sm[256];
    float s = 0.f;
    for (int r = threadIdx.x; r < ROWS_; r += 256)
        s += logf(g_sumexp[r]) - g_tgt[r];
    sm[threadIdx.x] = s;
    __syncthreads();
    for (int st = 128; st; st >>= 1) {
        if (threadIdx.x < st) sm[threadIdx.x] += sm[threadIdx.x + st];
        __syncthreads();
    }
    if (threadIdx.x == 0) out[0] = sm[0] / 32.f;
}

// ---------------- host launcher ----------------
extern "C" void kernel_launch(void* const* d_in, const int* in_sizes, int n_in,
                              void* d_out, int out_size)
{
    (void)in_sizes; (void)n_in; (void)out_size;
    const int*   x        = (const int*)  d_in[0];
    const int*   y        = (const int*)  d_in[1];
    const float* encemb   = (const float*)d_in[2];
    const float* decemb   = (const float*)d_in[3];
    const float* enc_Wih0 = (const float*)d_in[4];
    const float* enc_Whh0 = (const float*)d_in[5];
    const float* enc_bih0 = (const float*)d_in[6];
    const float* enc_bhh0 = (const float*)d_in[7];
    const float* enc_Wih1 = (const float*)d_in[8];
    const float* enc_Whh1 = (const float*)d_in[9];
    const float* enc_bih1 = (const float*)d_in[10];
    const float* enc_bhh1 = (const float*)d_in[11];
    const float* dec_Wih0 = (const float*)d_in[12];
    const float* dec_Whh0 = (const float*)d_in[13];
    const float* dec_bih0 = (const float*)d_in[14];
    const float* dec_bhh0 = (const float*)d_in[15];
    const float* dec_Wih1 = (const float*)d_in[16];
    const float* dec_Whh1 = (const float*)d_in[17];
    const float* dec_bih1 = (const float*)d_in[18];
    const float* dec_bhh1 = (const float*)d_in[19];
    const float* Wout     = (const float*)d_in[20];
    const float* bout     = (const float*)d_in[21];
    float* out = (float*)d_out;

    const int PRE_SMEM  = (128 + 64) * XROW_ * 2;                     // 101,376
    const int SCAN_SMEM = 4 * BUFB_ + 16;                             // 137,232
    const int CE_SMEM   = 128 * SROW_ * 2 + 2 * 128 * CROW2_ * 2;     // 174,080
    cudaFuncSetAttribute(pre_gemm,    cudaFuncAttributeMaxDynamicSharedMemorySize, PRE_SMEM);
    cudaFuncSetAttribute(scan_kernel, cudaFuncAttributeMaxDynamicSharedMemorySize, SCAN_SMEM);
    cudaFuncSetAttribute(ce2,         cudaFuncAttributeMaxDynamicSharedMemorySize, CE_SMEM);

    // launch order: harness emits 2 launches before ours, so scan (our #3)
    // lands at global #5 where ncu -s 5 -c 1 samples.
    setup_kernel<<<256, 256>>>(enc_bih0, enc_bhh0, dec_bih0, dec_bhh0,      // 0
                               enc_bih1, enc_bhh1, dec_bih1, dec_bhh1);

    Ptrs6 p6;
    p6.p[0] = enc_Whh0; p6.p[1] = enc_Wih1; p6.p[2] = enc_Whh1;
    p6.p[3] = dec_Whh0; p6.p[4] = dec_Wih1; p6.p[5] = dec_Whh1;
    const int GC = (NPAD_ * (SROW_ / 2) + 255) / 256;
    conv_gate_all<<<dim3(GC, 6), 256>>>(p6);                                 // 1

    pre_gemm<<<dim3(33, 32), 256, PRE_SMEM>>>(x, y, encemb, decemb,          // 2
                                              enc_Wih0, dec_Wih0);

    scan_kernel<<<SCANB_, 256, SCAN_SMEM>>>();                               // 3  <- ncu sample

    ce2<<<250, 256, CE_SMEM>>>(Wout, bout, y);                               // 4

    finalize_kernel<<<1, 256>>>(out);                                        // 5
}